// round 2
// baseline (speedup 1.0000x reference)
#include <cuda_runtime.h>

#define B_TOT    8192
#define T_LEN    512
#define F_IN     24
#define H_DIM    12
#define CHUNK    8
#define EPB      16           // batch elements per block
#define TPE      4            // threads per element (3 h-rows each)
#define NTHREADS (EPB * TPE)  // 64
#define NCHUNK   (T_LEN / CHUNK)
#define XS_STRIDE 28          // padded floats per (tt, elem) row; 28*e mod 32 covers banks
#define XS_BUF_FLOATS (CHUNK * EPB * XS_STRIDE)
#define SMEM_BYTES (2 * XS_BUF_FLOATS * 4)

typedef unsigned long long u64;

__device__ __forceinline__ unsigned smem_u32(const void* p) {
    return (unsigned)__cvta_generic_to_shared(p);
}
__device__ __forceinline__ void cp_async16(unsigned dst, const void* src) {
    asm volatile("cp.async.cg.shared.global [%0], [%1], 16;\n" :: "r"(dst), "l"(src));
}
__device__ __forceinline__ void cp_commit() {
    asm volatile("cp.async.commit_group;\n" ::: "memory");
}
template <int N> __device__ __forceinline__ void cp_wait() {
    asm volatile("cp.async.wait_group %0;\n" :: "n"(N) : "memory");
}

// ---- packed f32x2 helpers (FFMA2 path; ptxas only emits it from PTX f32x2) ----
__device__ __forceinline__ u64 pack2(float lo, float hi) {
    u64 d; asm("mov.b64 %0, {%1, %2};" : "=l"(d) : "f"(lo), "f"(hi)); return d;
}
__device__ __forceinline__ void unpack2(u64 d, float& lo, float& hi) {
    asm("mov.b64 {%0, %1}, %2;" : "=f"(lo), "=f"(hi) : "l"(d));
}
__device__ __forceinline__ u64 fma2(u64 a, u64 b, u64 c) {
    u64 d; asm("fma.rn.f32x2 %0, %1, %2, %3;" : "=l"(d) : "l"(a), "l"(b), "l"(c)); return d;
}

// tanh(x) = 1 - 2 * rcp(exp(2x) + 1);  5 instrs, saturates correctly at +/-inf.
__device__ __forceinline__ float tanh_fast(float x) {
    float e;
    asm("ex2.approx.f32 %0, %1;" : "=f"(e) : "f"(x * 2.885390082f)); // 2*log2(e)
    float r;
    asm("rcp.approx.f32 %0, %1;" : "=f"(r) : "f"(e + 1.0f));
    return fmaf(-2.0f, r, 1.0f);
}

__global__ void __launch_bounds__(NTHREADS) rnn_fused_kernel(
    const float* __restrict__ x,
    const float* __restrict__ W_ih, const float* __restrict__ b_ih,
    const float* __restrict__ W_hh, const float* __restrict__ b_hh,
    const float* __restrict__ W1,   const float* __restrict__ b1,
    const float* __restrict__ W2,   const float* __restrict__ b2,
    const float* __restrict__ W3,   const float* __restrict__ b3,
    float* __restrict__ out)
{
    extern __shared__ float xs[];  // [2][CHUNK][EPB][XS_STRIDE]
    __shared__ float sW1[144], sW2[144], sb1[12], sb2[12], sW3[12], sb3[1];

    const int tid  = threadIdx.x;
    const int e    = tid >> 2;        // element within block
    const int sub  = tid & 3;         // which 3 h-rows this thread owns
    const int lane = tid & 31;
    const int b    = blockIdx.x * EPB + e;
    const int j0   = sub * 3;

    // MLP weights -> shared (tiny, once)
    for (int i = tid; i < 144; i += NTHREADS) { sW1[i] = W1[i]; sW2[i] = W2[i]; }
    if (tid < 12) { sb1[tid] = b1[tid]; sb2[tid] = b2[tid]; sW3[tid] = W3[tid]; }
    if (tid == 0) sb3[0] = b3[0];

    // Per-thread recurrent weights, pre-packed along the contraction dim:
    //   wih2[c][p] = (W_ih[j][2p], W_ih[j][2p+1]),  p = 0..11
    //   whh2[c][p] = (W_hh[j][2p], W_hh[j][2p+1]),  p = 0..5
    u64 wih2[3][F_IN / 2], whh2[3][H_DIM / 2], biasp[3];
    #pragma unroll
    for (int c = 0; c < 3; c++) {
        const int j = j0 + c;
        #pragma unroll
        for (int p = 0; p < F_IN / 2; p++)
            wih2[c][p] = pack2(W_ih[j * F_IN + 2 * p], W_ih[j * F_IN + 2 * p + 1]);
        #pragma unroll
        for (int p = 0; p < H_DIM / 2; p++)
            whh2[c][p] = pack2(W_hh[j * H_DIM + 2 * p], W_hh[j * H_DIM + 2 * p + 1]);
        biasp[c] = pack2(b_ih[j] + b_hh[j], 0.0f);
    }

    const long xbase = (long)blockIdx.x * EPB * T_LEN * F_IN;

    // Stage a chunk of 8 timesteps for all EPB elements via cp.async.
    // 768 x 16B ops per chunk, 12 per thread, consecutive threads read
    // contiguous global bytes (each element contributes 768B contiguous).
    auto load_chunk = [&](int bufidx, int c) {
        float* dstbuf = xs + bufidx * XS_BUF_FLOATS;
        #pragma unroll
        for (int i = 0; i < 12; i++) {
            int idx = tid + NTHREADS * i;         // 0..767
            int ee  = idx / 48;
            int r   = idx % 48;
            int tt  = r / 6;
            int q   = r % 6;
            const float* src = x + xbase + ((long)ee * T_LEN + (c * CHUNK + tt)) * F_IN + q * 4;
            unsigned dst = smem_u32(dstbuf + (tt * EPB + ee) * XS_STRIDE + q * 4);
            cp_async16(dst, src);
        }
        cp_commit();
    };

    u64 hp[H_DIM / 2];                 // h packed as (h[2k], h[2k+1])
    #pragma unroll
    for (int k = 0; k < H_DIM / 2; k++) hp[k] = 0ull;

    load_chunk(0, 0);

    for (int c = 0; c < NCHUNK; c++) {
        __syncthreads();  // (A) everyone done reading the buffer we overwrite
        if (c + 1 < NCHUNK) { load_chunk((c + 1) & 1, c + 1); cp_wait<1>(); }
        else                { cp_wait<0>(); }
        __syncthreads();  // (B) buf[c&1] visible

        const float* buf = xs + (c & 1) * XS_BUF_FLOATS;
        #pragma unroll
        for (int tt = 0; tt < CHUNK; tt++) {
            // x row as 6 x LDS.128, each yielding two packed f32x2 operands
            const ulonglong2* xr = (const ulonglong2*)(buf + (tt * EPB + e) * XS_STRIDE);
            u64 acc[3] = {biasp[0], biasp[1], biasp[2]};
            #pragma unroll
            for (int q = 0; q < 6; q++) {
                ulonglong2 v = xr[q];
                #pragma unroll
                for (int cc = 0; cc < 3; cc++) {
                    acc[cc] = fma2(wih2[cc][2 * q + 0], v.x, acc[cc]);
                    acc[cc] = fma2(wih2[cc][2 * q + 1], v.y, acc[cc]);
                }
            }
            // recurrence: 6 packed FMAs per row
            #pragma unroll
            for (int p = 0; p < H_DIM / 2; p++) {
                #pragma unroll
                for (int cc = 0; cc < 3; cc++)
                    acc[cc] = fma2(whh2[cc][p], hp[p], acc[cc]);
            }
            // horizontal combine + tanh
            float hl[3];
            #pragma unroll
            for (int cc = 0; cc < 3; cc++) {
                float lo, hi; unpack2(acc[cc], lo, hi);
                hl[cc] = tanh_fast(lo + hi);
            }
            // h exchange inside the quad: 12 shfl, repacked into 6 pairs
            const int qbase = lane & ~3;
            float hs[H_DIM];
            #pragma unroll
            for (int s = 0; s < 4; s++) {
                #pragma unroll
                for (int cc = 0; cc < 3; cc++)
                    hs[s * 3 + cc] = __shfl_sync(0xffffffffu, hl[cc], qbase + s);
            }
            #pragma unroll
            for (int p = 0; p < H_DIM / 2; p++)
                hp[p] = pack2(hs[2 * p], hs[2 * p + 1]);
        }
    }

    // MLP head: one thread per element
    if (sub == 0) {
        float h_all[H_DIM];
        #pragma unroll
        for (int p = 0; p < H_DIM / 2; p++) unpack2(hp[p], h_all[2 * p], h_all[2 * p + 1]);
        float o1[H_DIM], o2[H_DIM];
        #pragma unroll
        for (int j = 0; j < H_DIM; j++) {
            float s = sb1[j];
            #pragma unroll
            for (int k = 0; k < H_DIM; k++) s = fmaf(sW1[j * H_DIM + k], h_all[k], s);
            o1[j] = fmaxf(s, 0.0f);
        }
        #pragma unroll
        for (int j = 0; j < H_DIM; j++) {
            float s = sb2[j];
            #pragma unroll
            for (int k = 0; k < H_DIM; k++) s = fmaf(sW2[j * H_DIM + k], o1[k], s);
            o2[j] = fmaxf(s, 0.0f);
        }
        float s = sb3[0];
        #pragma unroll
        for (int k = 0; k < H_DIM; k++) s = fmaf(sW3[k], o2[k], s);
        out[b] = s;
    }
}

extern "C" void kernel_launch(void* const* d_in, const int* in_sizes, int n_in,
                              void* d_out, int out_size) {
    (void)in_sizes; (void)n_in; (void)out_size;
    const float* x    = (const float*)d_in[0];
    const float* W_ih = (const float*)d_in[1];
    const float* b_ih = (const float*)d_in[2];
    const float* W_hh = (const float*)d_in[3];
    const float* b_hh = (const float*)d_in[4];
    const float* W1   = (const float*)d_in[5];
    const float* b1   = (const float*)d_in[6];
    const float* W2   = (const float*)d_in[7];
    const float* b2   = (const float*)d_in[8];
    const float* W3   = (const float*)d_in[9];
    const float* b3   = (const float*)d_in[10];
    float* out = (float*)d_out;

    cudaFuncSetAttribute(rnn_fused_kernel,
                         cudaFuncAttributeMaxDynamicSharedMemorySize, SMEM_BYTES);

    dim3 grid(B_TOT / EPB);   // 512 blocks
    dim3 block(NTHREADS);     // 64 threads
    rnn_fused_kernel<<<grid, block, SMEM_BYTES>>>(
        x, W_ih, b_ih, W_hh, b_hh, W1, b1, W2, b2, W3, b3, out);
}